// round 9
// baseline (speedup 1.0000x reference)
#include <cuda_runtime.h>
#include <cuda_bf16.h>
#include <math.h>

// Problem shape
#define B_ 32
#define N_ 577
#define C_ 768
#define H_ 3072
#define ROWS (B_ * N_)          // 18464
#define EPS 1e-5f
#define ATTN_LD 580             // padded leading dim (multiple of 4 -> 16B aligned rows)

// ---------------- scratch (device globals; no allocation allowed) ------------
__device__ float g_h   [ROWS * C_];             // LN1 output
__device__ float g_qkv [ROWS * 3 * C_];         // qkv
__device__ float g_attn[B_ * N_ * ATTN_LD];     // scores / attn (padded rows)
__device__ float g_y   [ROWS * C_];             // attn @ v
__device__ float g_yp  [ROWS * C_];             // permuted y
__device__ float g_x1  [ROWS * C_];             // 2*(proj out)
__device__ float g_m0  [ROWS * C_];             // LN2 output
__device__ float g_m1  [ROWS * H_];             // gelu(fc1)

// ---------------- block reduce helper ----------------------------------------
__device__ __forceinline__ float block_reduce(float v, float* shm, bool do_max) {
    #pragma unroll
    for (int o = 16; o; o >>= 1) {
        float t = __shfl_xor_sync(0xffffffffu, v, o);
        v = do_max ? fmaxf(v, t) : (v + t);
    }
    int warp = threadIdx.x >> 5, lane = threadIdx.x & 31;
    if (lane == 0) shm[warp] = v;
    __syncthreads();
    int nw = blockDim.x >> 5;
    float r = (threadIdx.x < nw) ? shm[threadIdx.x] : (do_max ? -INFINITY : 0.f);
    if (warp == 0) {
        #pragma unroll
        for (int o = 4; o; o >>= 1) {
            float t = __shfl_xor_sync(0xffffffffu, r, o);
            r = do_max ? fmaxf(r, t) : (r + t);
        }
        if (lane == 0) shm[0] = r;
    }
    __syncthreads();
    r = shm[0];
    __syncthreads();
    return r;
}

// ---------------- layernorm ---------------------------------------------------
__global__ void layernorm_kernel(const float* __restrict__ x,
                                 const float* __restrict__ w,
                                 const float* __restrict__ b,
                                 float* __restrict__ out) {
    __shared__ float shm[8];
    long long row = blockIdx.x;
    const float* xr = x + row * C_;
    float s = 0.f, s2 = 0.f;
    for (int i = threadIdx.x; i < C_; i += blockDim.x) {
        float v = xr[i];
        s += v; s2 += v * v;
    }
    s  = block_reduce(s,  shm, false);
    s2 = block_reduce(s2, shm, false);
    float mu  = s * (1.f / C_);
    float var = s2 * (1.f / C_) - mu * mu;
    float inv = rsqrtf(var + EPS);
    float* orow = out + row * C_;
    for (int i = threadIdx.x; i < C_; i += blockDim.x)
        orow[i] = (xr[i] - mu) * inv * w[i] + b[i];
}

// ---------------- SGEMM: C = epi(alpha * A @ op(B)) --------------------------
// TRANS_B=1: B is [N,K] row-major (NT).  TRANS_B=0: B is [K,N] row-major (NN).
// EPI: 0 -> alpha*acc
//      1 -> 2*(acc + bias[n])
//      2 -> gelu_exact(acc + bias[n])
//      3 -> res[m,n] + acc + bias[n]
#define BM 128
#define BN 128
#define BK 8
#define TM 8
#define TN 8

template<int TRANS_B, int EPI>
__global__ __launch_bounds__(256)
void sgemm_kernel(const float* __restrict__ A, const float* __restrict__ Bp,
                  float* __restrict__ C,
                  int M, int N, int K,
                  int lda, int ldb, int ldc,
                  long long sA, long long sB, long long sC,
                  const float* __restrict__ bias,
                  const float* __restrict__ res,
                  float alpha)
{
    __shared__ float As[BK][BM];
    __shared__ float Bs[BK][BN];

    const float* Ab = A  + (long long)blockIdx.z * sA;
    const float* Bb = Bp + (long long)blockIdx.z * sB;
    float*       Cb = C  + (long long)blockIdx.z * sC;
    const float* Rb = res ? res + (long long)blockIdx.z * sC : nullptr;

    int m0 = blockIdx.y * BM;
    int n0 = blockIdx.x * BN;
    int tid = threadIdx.x;
    int tr = tid / 16;   // 0..15
    int tc = tid % 16;   // 0..15

    float acc[TM][TN];
    #pragma unroll
    for (int i = 0; i < TM; i++)
        #pragma unroll
        for (int j = 0; j < TN; j++) acc[i][j] = 0.f;

    int a_row = tid >> 1;          // 0..127
    int a_col = (tid & 1) * 4;     // 0 or 4
    int b_row, b_col;
    if (TRANS_B) { b_row = tid >> 1;  b_col = (tid & 1) * 4; }
    else         { b_row = tid >> 5;  b_col = (tid & 31) * 4; }

    for (int k0 = 0; k0 < K; k0 += BK) {
        // A tile -> As[k][m]
        {
            int gm = m0 + a_row;
            if (gm < M && (k0 + a_col + 3) < K) {
                float4 v = *reinterpret_cast<const float4*>(
                    Ab + (long long)gm * lda + k0 + a_col);
                As[a_col + 0][a_row] = v.x;
                As[a_col + 1][a_row] = v.y;
                As[a_col + 2][a_row] = v.z;
                As[a_col + 3][a_row] = v.w;
            } else {
                #pragma unroll
                for (int j = 0; j < 4; j++) {
                    int gk = k0 + a_col + j;
                    As[a_col + j][a_row] =
                        (gm < M && gk < K) ? Ab[(long long)gm * lda + gk] : 0.f;
                }
            }
        }
        // B tile
        if (TRANS_B) {
            int gn = n0 + b_row;
            if (gn < N && (k0 + b_col + 3) < K) {
                float4 v = *reinterpret_cast<const float4*>(
                    Bb + (long long)gn * ldb + k0 + b_col);
                Bs[b_col + 0][b_row] = v.x;
                Bs[b_col + 1][b_row] = v.y;
                Bs[b_col + 2][b_row] = v.z;
                Bs[b_col + 3][b_row] = v.w;
            } else {
                #pragma unroll
                for (int j = 0; j < 4; j++) {
                    int gk = k0 + b_col + j;
                    Bs[b_col + j][b_row] =
                        (gn < N && gk < K) ? Bb[(long long)gn * ldb + gk] : 0.f;
                }
            }
        } else {
            int gk = k0 + b_row;
            if (gk < K && (n0 + b_col + 3) < N) {
                float4 v = *reinterpret_cast<const float4*>(
                    Bb + (long long)gk * ldb + n0 + b_col);
                Bs[b_row][b_col + 0] = v.x;
                Bs[b_row][b_col + 1] = v.y;
                Bs[b_row][b_col + 2] = v.z;
                Bs[b_row][b_col + 3] = v.w;
            } else {
                #pragma unroll
                for (int j = 0; j < 4; j++) {
                    int gn = n0 + b_col + j;
                    Bs[b_row][b_col + j] =
                        (gk < K && gn < N) ? Bb[(long long)gk * ldb + gn] : 0.f;
                }
            }
        }
        __syncthreads();

        #pragma unroll
        for (int kk = 0; kk < BK; kk++) {
            float a_frag[TM], b_frag[TN];
            float4 av0 = *reinterpret_cast<const float4*>(&As[kk][tr * TM]);
            float4 av1 = *reinterpret_cast<const float4*>(&As[kk][tr * TM + 4]);
            a_frag[0]=av0.x; a_frag[1]=av0.y; a_frag[2]=av0.z; a_frag[3]=av0.w;
            a_frag[4]=av1.x; a_frag[5]=av1.y; a_frag[6]=av1.z; a_frag[7]=av1.w;
            float4 bv0 = *reinterpret_cast<const float4*>(&Bs[kk][tc * TN]);
            float4 bv1 = *reinterpret_cast<const float4*>(&Bs[kk][tc * TN + 4]);
            b_frag[0]=bv0.x; b_frag[1]=bv0.y; b_frag[2]=bv0.z; b_frag[3]=bv0.w;
            b_frag[4]=bv1.x; b_frag[5]=bv1.y; b_frag[6]=bv1.z; b_frag[7]=bv1.w;
            #pragma unroll
            for (int i = 0; i < TM; i++)
                #pragma unroll
                for (int j = 0; j < TN; j++)
                    acc[i][j] += a_frag[i] * b_frag[j];
        }
        __syncthreads();
    }

    #pragma unroll
    for (int i = 0; i < TM; i++) {
        int gm = m0 + tr * TM + i;
        if (gm >= M) continue;
        #pragma unroll
        for (int j = 0; j < TN; j++) {
            int gn = n0 + tc * TN + j;
            if (gn >= N) continue;
            float v = acc[i][j];
            if (EPI == 0) {
                v *= alpha;
            } else if (EPI == 1) {
                v = 2.f * (v + bias[gn]);
            } else if (EPI == 2) {
                v += bias[gn];
                v = 0.5f * v * (1.f + erff(v * 0.7071067811865475f));
            } else if (EPI == 3) {
                v = Rb[(long long)gm * ldc + gn] + v + bias[gn];
            }
            Cb[(long long)gm * ldc + gn] = v;
        }
    }
}

// ---------------- softmax over last dim (len N_, padded rows) -----------------
__global__ void softmax_kernel(float* __restrict__ attn) {
    __shared__ float shm[8];
    long long row = blockIdx.x;                 // b*N_ + n
    float* p = attn + row * ATTN_LD;
    float mx = -INFINITY;
    for (int i = threadIdx.x; i < N_; i += blockDim.x) mx = fmaxf(mx, p[i]);
    mx = block_reduce(mx, shm, true);
    float s = 0.f;
    for (int i = threadIdx.x; i < N_; i += blockDim.x) {
        float e = expf(p[i] - mx);
        p[i] = e;
        s += e;
    }
    s = block_reduce(s, shm, false);
    float inv = 1.f / s;
    for (int i = threadIdx.x; i < N_; i += blockDim.x) p[i] *= inv;
    // zero the pad so the AV GEMM can read garbage-free (it masks by K anyway)
    for (int i = N_ + threadIdx.x; i < ATTN_LD; i += blockDim.x) p[i] = 0.f;
}

// ---------------- token_attn slice: attn[:, 0, 1:] ---------------------------
__global__ void token_attn_kernel(const float* __restrict__ attn,
                                  float* __restrict__ out) {
    int idx = blockIdx.x * blockDim.x + threadIdx.x;   // b*576 + i
    if (idx >= B_ * (N_ - 1)) return;
    int b = idx / (N_ - 1);
    int i = idx % (N_ - 1);
    out[idx] = attn[(long long)b * N_ * ATTN_LD + 1 + i];
}

// ---------------- permute: yp[b, f] = y[b, f%577, f/577] ---------------------
__global__ void permute_kernel(const float* __restrict__ y,
                               float* __restrict__ yp) {
    long long idx = (long long)blockIdx.x * blockDim.x + threadIdx.x;
    const long long per = (long long)N_ * C_;
    if (idx >= (long long)B_ * per) return;
    long long b = idx / per;
    long long f = idx % per;
    long long j = f % N_;     // source token
    long long i = f / N_;     // source channel
    yp[idx] = y[b * per + j * C_ + i];
}

// ---------------- launcher ----------------------------------------------------
extern "C" void kernel_launch(void* const* d_in, const int* in_sizes, int n_in,
                              void* d_out, int out_size) {
    const float* x      = (const float*)d_in[0];
    const float* n1w    = (const float*)d_in[1];
    const float* n1b    = (const float*)d_in[2];
    const float* qkv_w  = (const float*)d_in[3];
    const float* proj_w = (const float*)d_in[4];
    const float* proj_b = (const float*)d_in[5];
    const float* n2w    = (const float*)d_in[6];
    const float* n2b    = (const float*)d_in[7];
    const float* fc1_w  = (const float*)d_in[8];
    const float* fc1_b  = (const float*)d_in[9];
    const float* fc2_w  = (const float*)d_in[10];
    const float* fc2_b  = (const float*)d_in[11];
    float* out = (float*)d_out;
    float* out_tok = out + (long long)ROWS * C_;

    float *h, *qkv, *attn, *y, *yp, *x1, *m0, *m1;
    cudaGetSymbolAddress((void**)&h,    g_h);
    cudaGetSymbolAddress((void**)&qkv,  g_qkv);
    cudaGetSymbolAddress((void**)&attn, g_attn);
    cudaGetSymbolAddress((void**)&y,    g_y);
    cudaGetSymbolAddress((void**)&yp,   g_yp);
    cudaGetSymbolAddress((void**)&x1,   g_x1);
    cudaGetSymbolAddress((void**)&m0,   g_m0);
    cudaGetSymbolAddress((void**)&m1,   g_m1);

    const float scale = 1.0f / sqrtf((float)C_);

    // 1) LN1
    layernorm_kernel<<<ROWS, 256>>>(x, n1w, n1b, h);

    // 2) qkv = h @ qkv_w^T   [18464 x 2304], K=768
    {
        dim3 grid((3 * C_ + BN - 1) / BN, (ROWS + BM - 1) / BM, 1);
        sgemm_kernel<1, 0><<<grid, 256>>>(h, qkv_w, qkv,
                                          ROWS, 3 * C_, C_,
                                          C_, C_, 3 * C_,
                                          0, 0, 0, nullptr, nullptr, 1.0f);
    }

    // 3) scores = scale * q @ k^T   batched over B_  [577 x 577 (ld 580)], K=768
    {
        dim3 grid((N_ + BN - 1) / BN, (N_ + BM - 1) / BM, B_);
        sgemm_kernel<1, 0><<<grid, 256>>>(qkv /*q*/, qkv + C_ /*k*/, attn,
                                          N_, N_, C_,
                                          3 * C_, 3 * C_, ATTN_LD,
                                          (long long)N_ * 3 * C_,
                                          (long long)N_ * 3 * C_,
                                          (long long)N_ * ATTN_LD,
                                          nullptr, nullptr, scale);
    }

    // 4) softmax rows
    softmax_kernel<<<B_ * N_, 256>>>(attn);

    // 5) token_attn out
    token_attn_kernel<<<(B_ * (N_ - 1) + 255) / 256, 256>>>(attn, out_tok);

    // 6) y = attn @ v   batched  [577 x 768], K=577  (A rows padded to 580)
    {
        dim3 grid((C_ + BN - 1) / BN, (N_ + BM - 1) / BM, B_);
        sgemm_kernel<0, 0><<<grid, 256>>>(attn, qkv + 2 * C_ /*v*/, y,
                                          N_, C_, N_,
                                          ATTN_LD, 3 * C_, C_,
                                          (long long)N_ * ATTN_LD,
                                          (long long)N_ * 3 * C_,
                                          (long long)N_ * C_,
                                          nullptr, nullptr, 1.0f);
    }

    // 7) permute (transpose(0,2,1).reshape)
    {
        long long total = (long long)ROWS * C_;
        permute_kernel<<<(unsigned)((total + 255) / 256), 256>>>(y, yp);
    }

    // 8) x1 = 2*(yp @ proj_w^T + proj_b)
    {
        dim3 grid((C_ + BN - 1) / BN, (ROWS + BM - 1) / BM, 1);
        sgemm_kernel<1, 1><<<grid, 256>>>(yp, proj_w, x1,
                                          ROWS, C_, C_,
                                          C_, C_, C_,
                                          0, 0, 0, proj_b, nullptr, 1.0f);
    }

    // 9) LN2
    layernorm_kernel<<<ROWS, 256>>>(x1, n2w, n2b, m0);

    // 10) m1 = gelu(m0 @ fc1_w^T + fc1_b)   [18464 x 3072], K=768
    {
        dim3 grid((H_ + BN - 1) / BN, (ROWS + BM - 1) / BM, 1);
        sgemm_kernel<1, 2><<<grid, 256>>>(m0, fc1_w, m1,
                                          ROWS, H_, C_,
                                          C_, C_, H_,
                                          0, 0, 0, fc1_b, nullptr, 1.0f);
    }

    // 11) out = x1 + m1 @ fc2_w^T + fc2_b   [18464 x 768], K=3072
    {
        dim3 grid((C_ + BN - 1) / BN, (ROWS + BM - 1) / BM, 1);
        sgemm_kernel<1, 3><<<grid, 256>>>(m1, fc2_w, out,
                                          ROWS, C_, H_,
                                          H_, H_, C_,
                                          0, 0, 0, fc2_b, x1, 1.0f);
    }
}

// round 10
// speedup vs baseline: 1.0028x; 1.0028x over previous
#include <cuda_runtime.h>
#include <cuda_bf16.h>
#include <math.h>

// Problem shape
#define B_ 32
#define N_ 577
#define C_ 768
#define H_ 3072
#define ROWS (B_ * N_)          // 18464
#define EPS 1e-5f
#define ATTN_LD 580             // padded leading dim (multiple of 4 -> 16B aligned rows)

// ---------------- scratch (device globals; no allocation allowed) ------------
__device__ float g_h   [ROWS * C_];             // LN1 output
__device__ float g_qkv [ROWS * 3 * C_];         // qkv
__device__ float g_attn[B_ * N_ * ATTN_LD];     // scores / attn (padded rows)
__device__ float g_y   [ROWS * C_];             // attn @ v
__device__ float g_yp  [ROWS * C_];             // permuted y
__device__ float g_x1  [ROWS * C_];             // 2*(proj out)
__device__ float g_m0  [ROWS * C_];             // LN2 output
__device__ float g_m1  [ROWS * H_];             // gelu(fc1)

// ---------------- block reduce helper ----------------------------------------
__device__ __forceinline__ float block_reduce(float v, float* shm, bool do_max) {
    #pragma unroll
    for (int o = 16; o; o >>= 1) {
        float t = __shfl_xor_sync(0xffffffffu, v, o);
        v = do_max ? fmaxf(v, t) : (v + t);
    }
    int warp = threadIdx.x >> 5, lane = threadIdx.x & 31;
    if (lane == 0) shm[warp] = v;
    __syncthreads();
    int nw = blockDim.x >> 5;
    float r = (threadIdx.x < nw) ? shm[threadIdx.x] : (do_max ? -INFINITY : 0.f);
    if (warp == 0) {
        #pragma unroll
        for (int o = 4; o; o >>= 1) {
            float t = __shfl_xor_sync(0xffffffffu, r, o);
            r = do_max ? fmaxf(r, t) : (r + t);
        }
        if (lane == 0) shm[0] = r;
    }
    __syncthreads();
    r = shm[0];
    __syncthreads();
    return r;
}

// ---------------- layernorm ---------------------------------------------------
__global__ void layernorm_kernel(const float* __restrict__ x,
                                 const float* __restrict__ w,
                                 const float* __restrict__ b,
                                 float* __restrict__ out) {
    __shared__ float shm[8];
    long long row = blockIdx.x;
    const float* xr = x + row * C_;
    float s = 0.f, s2 = 0.f;
    for (int i = threadIdx.x; i < C_; i += blockDim.x) {
        float v = xr[i];
        s += v; s2 += v * v;
    }
    s  = block_reduce(s,  shm, false);
    s2 = block_reduce(s2, shm, false);
    float mu  = s * (1.f / C_);
    float var = s2 * (1.f / C_) - mu * mu;
    float inv = rsqrtf(var + EPS);
    float* orow = out + row * C_;
    for (int i = threadIdx.x; i < C_; i += blockDim.x)
        orow[i] = (xr[i] - mu) * inv * w[i] + b[i];
}

// ---------------- SGEMM: C = epi(alpha * A @ op(B)) --------------------------
// TRANS_B=1: B is [N,K] row-major (NT).  TRANS_B=0: B is [K,N] row-major (NN).
// EPI: 0 -> alpha*acc
//      1 -> 2*(acc + bias[n])
//      2 -> gelu_exact(acc + bias[n])
//      3 -> res[m,n] + acc + bias[n]
#define BM 128
#define BN 128
#define BK 8
#define TM 8
#define TN 8

template<int TRANS_B, int EPI>
__global__ __launch_bounds__(256)
void sgemm_kernel(const float* __restrict__ A, const float* __restrict__ Bp,
                  float* __restrict__ C,
                  int M, int N, int K,
                  int lda, int ldb, int ldc,
                  long long sA, long long sB, long long sC,
                  const float* __restrict__ bias,
                  const float* __restrict__ res,
                  float alpha)
{
    __shared__ float As[BK][BM];
    __shared__ float Bs[BK][BN];

    const float* Ab = A  + (long long)blockIdx.z * sA;
    const float* Bb = Bp + (long long)blockIdx.z * sB;
    float*       Cb = C  + (long long)blockIdx.z * sC;
    const float* Rb = res ? res + (long long)blockIdx.z * sC : nullptr;

    int m0 = blockIdx.y * BM;
    int n0 = blockIdx.x * BN;
    int tid = threadIdx.x;
    int tr = tid / 16;   // 0..15
    int tc = tid % 16;   // 0..15

    float acc[TM][TN];
    #pragma unroll
    for (int i = 0; i < TM; i++)
        #pragma unroll
        for (int j = 0; j < TN; j++) acc[i][j] = 0.f;

    int a_row = tid >> 1;          // 0..127
    int a_col = (tid & 1) * 4;     // 0 or 4
    int b_row, b_col;
    if (TRANS_B) { b_row = tid >> 1;  b_col = (tid & 1) * 4; }
    else         { b_row = tid >> 5;  b_col = (tid & 31) * 4; }

    for (int k0 = 0; k0 < K; k0 += BK) {
        // A tile -> As[k][m]
        {
            int gm = m0 + a_row;
            if (gm < M && (k0 + a_col + 3) < K) {
                float4 v = *reinterpret_cast<const float4*>(
                    Ab + (long long)gm * lda + k0 + a_col);
                As[a_col + 0][a_row] = v.x;
                As[a_col + 1][a_row] = v.y;
                As[a_col + 2][a_row] = v.z;
                As[a_col + 3][a_row] = v.w;
            } else {
                #pragma unroll
                for (int j = 0; j < 4; j++) {
                    int gk = k0 + a_col + j;
                    As[a_col + j][a_row] =
                        (gm < M && gk < K) ? Ab[(long long)gm * lda + gk] : 0.f;
                }
            }
        }
        // B tile
        if (TRANS_B) {
            int gn = n0 + b_row;
            if (gn < N && (k0 + b_col + 3) < K) {
                float4 v = *reinterpret_cast<const float4*>(
                    Bb + (long long)gn * ldb + k0 + b_col);
                Bs[b_col + 0][b_row] = v.x;
                Bs[b_col + 1][b_row] = v.y;
                Bs[b_col + 2][b_row] = v.z;
                Bs[b_col + 3][b_row] = v.w;
            } else {
                #pragma unroll
                for (int j = 0; j < 4; j++) {
                    int gk = k0 + b_col + j;
                    Bs[b_col + j][b_row] =
                        (gn < N && gk < K) ? Bb[(long long)gn * ldb + gk] : 0.f;
                }
            }
        } else {
            int gk = k0 + b_row;
            if (gk < K && (n0 + b_col + 3) < N) {
                float4 v = *reinterpret_cast<const float4*>(
                    Bb + (long long)gk * ldb + n0 + b_col);
                Bs[b_row][b_col + 0] = v.x;
                Bs[b_row][b_col + 1] = v.y;
                Bs[b_row][b_col + 2] = v.z;
                Bs[b_row][b_col + 3] = v.w;
            } else {
                #pragma unroll
                for (int j = 0; j < 4; j++) {
                    int gn = n0 + b_col + j;
                    Bs[b_row][b_col + j] =
                        (gk < K && gn < N) ? Bb[(long long)gk * ldb + gn] : 0.f;
                }
            }
        }
        __syncthreads();

        #pragma unroll
        for (int kk = 0; kk < BK; kk++) {
            float a_frag[TM], b_frag[TN];
            float4 av0 = *reinterpret_cast<const float4*>(&As[kk][tr * TM]);
            float4 av1 = *reinterpret_cast<const float4*>(&As[kk][tr * TM + 4]);
            a_frag[0]=av0.x; a_frag[1]=av0.y; a_frag[2]=av0.z; a_frag[3]=av0.w;
            a_frag[4]=av1.x; a_frag[5]=av1.y; a_frag[6]=av1.z; a_frag[7]=av1.w;
            float4 bv0 = *reinterpret_cast<const float4*>(&Bs[kk][tc * TN]);
            float4 bv1 = *reinterpret_cast<const float4*>(&Bs[kk][tc * TN + 4]);
            b_frag[0]=bv0.x; b_frag[1]=bv0.y; b_frag[2]=bv0.z; b_frag[3]=bv0.w;
            b_frag[4]=bv1.x; b_frag[5]=bv1.y; b_frag[6]=bv1.z; b_frag[7]=bv1.w;
            #pragma unroll
            for (int i = 0; i < TM; i++)
                #pragma unroll
                for (int j = 0; j < TN; j++)
                    acc[i][j] += a_frag[i] * b_frag[j];
        }
        __syncthreads();
    }

    #pragma unroll
    for (int i = 0; i < TM; i++) {
        int gm = m0 + tr * TM + i;
        if (gm >= M) continue;
        #pragma unroll
        for (int j = 0; j < TN; j++) {
            int gn = n0 + tc * TN + j;
            if (gn >= N) continue;
            float v = acc[i][j];
            if (EPI == 0) {
                v *= alpha;
            } else if (EPI == 1) {
                v = 2.f * (v + bias[gn]);
            } else if (EPI == 2) {
                v += bias[gn];
                v = 0.5f * v * (1.f + erff(v * 0.7071067811865475f));
            } else if (EPI == 3) {
                v = Rb[(long long)gm * ldc + gn] + v + bias[gn];
            }
            Cb[(long long)gm * ldc + gn] = v;
        }
    }
}

// ---------------- softmax over last dim (len N_, padded rows) -----------------
__global__ void softmax_kernel(float* __restrict__ attn) {
    __shared__ float shm[8];
    long long row = blockIdx.x;                 // b*N_ + n
    float* p = attn + row * ATTN_LD;
    float mx = -INFINITY;
    for (int i = threadIdx.x; i < N_; i += blockDim.x) mx = fmaxf(mx, p[i]);
    mx = block_reduce(mx, shm, true);
    float s = 0.f;
    for (int i = threadIdx.x; i < N_; i += blockDim.x) {
        float e = expf(p[i] - mx);
        p[i] = e;
        s += e;
    }
    s = block_reduce(s, shm, false);
    float inv = 1.f / s;
    for (int i = threadIdx.x; i < N_; i += blockDim.x) p[i] *= inv;
    // zero the pad so the AV GEMM can read garbage-free (it masks by K anyway)
    for (int i = N_ + threadIdx.x; i < ATTN_LD; i += blockDim.x) p[i] = 0.f;
}

// ---------------- token_attn slice: attn[:, 0, 1:] ---------------------------
__global__ void token_attn_kernel(const float* __restrict__ attn,
                                  float* __restrict__ out) {
    int idx = blockIdx.x * blockDim.x + threadIdx.x;   // b*576 + i
    if (idx >= B_ * (N_ - 1)) return;
    int b = idx / (N_ - 1);
    int i = idx % (N_ - 1);
    out[idx] = attn[(long long)b * N_ * ATTN_LD + 1 + i];
}

// ---------------- permute: yp[b, f] = y[b, f%577, f/577] ---------------------
__global__ void permute_kernel(const float* __restrict__ y,
                               float* __restrict__ yp) {
    long long idx = (long long)blockIdx.x * blockDim.x + threadIdx.x;
    const long long per = (long long)N_ * C_;
    if (idx >= (long long)B_ * per) return;
    long long b = idx / per;
    long long f = idx % per;
    long long j = f % N_;     // source token
    long long i = f / N_;     // source channel
    yp[idx] = y[b * per + j * C_ + i];
}

// ---------------- launcher ----------------------------------------------------
extern "C" void kernel_launch(void* const* d_in, const int* in_sizes, int n_in,
                              void* d_out, int out_size) {
    const float* x      = (const float*)d_in[0];
    const float* n1w    = (const float*)d_in[1];
    const float* n1b    = (const float*)d_in[2];
    const float* qkv_w  = (const float*)d_in[3];
    const float* proj_w = (const float*)d_in[4];
    const float* proj_b = (const float*)d_in[5];
    const float* n2w    = (const float*)d_in[6];
    const float* n2b    = (const float*)d_in[7];
    const float* fc1_w  = (const float*)d_in[8];
    const float* fc1_b  = (const float*)d_in[9];
    const float* fc2_w  = (const float*)d_in[10];
    const float* fc2_b  = (const float*)d_in[11];
    float* out = (float*)d_out;
    float* out_tok = out + (long long)ROWS * C_;

    float *h, *qkv, *attn, *y, *yp, *x1, *m0, *m1;
    cudaGetSymbolAddress((void**)&h,    g_h);
    cudaGetSymbolAddress((void**)&qkv,  g_qkv);
    cudaGetSymbolAddress((void**)&attn, g_attn);
    cudaGetSymbolAddress((void**)&y,    g_y);
    cudaGetSymbolAddress((void**)&yp,   g_yp);
    cudaGetSymbolAddress((void**)&x1,   g_x1);
    cudaGetSymbolAddress((void**)&m0,   g_m0);
    cudaGetSymbolAddress((void**)&m1,   g_m1);

    const float scale = 1.0f / sqrtf((float)C_);

    // 1) LN1
    layernorm_kernel<<<ROWS, 256>>>(x, n1w, n1b, h);

    // 2) qkv = h @ qkv_w^T   [18464 x 2304], K=768
    {
        dim3 grid((3 * C_ + BN - 1) / BN, (ROWS + BM - 1) / BM, 1);
        sgemm_kernel<1, 0><<<grid, 256>>>(h, qkv_w, qkv,
                                          ROWS, 3 * C_, C_,
                                          C_, C_, 3 * C_,
                                          0, 0, 0, nullptr, nullptr, 1.0f);
    }

    // 3) scores = scale * q @ k^T   batched over B_  [577 x 577 (ld 580)], K=768
    {
        dim3 grid((N_ + BN - 1) / BN, (N_ + BM - 1) / BM, B_);
        sgemm_kernel<1, 0><<<grid, 256>>>(qkv /*q*/, qkv + C_ /*k*/, attn,
                                          N_, N_, C_,
                                          3 * C_, 3 * C_, ATTN_LD,
                                          (long long)N_ * 3 * C_,
                                          (long long)N_ * 3 * C_,
                                          (long long)N_ * ATTN_LD,
                                          nullptr, nullptr, scale);
    }

    // 4) softmax rows
    softmax_kernel<<<B_ * N_, 256>>>(attn);

    // 5) token_attn out
    token_attn_kernel<<<(B_ * (N_ - 1) + 255) / 256, 256>>>(attn, out_tok);

    // 6) y = attn @ v   batched  [577 x 768], K=577  (A rows padded to 580)
    {
        dim3 grid((C_ + BN - 1) / BN, (N_ + BM - 1) / BM, B_);
        sgemm_kernel<0, 0><<<grid, 256>>>(attn, qkv + 2 * C_ /*v*/, y,
                                          N_, C_, N_,
                                          ATTN_LD, 3 * C_, C_,
                                          (long long)N_ * ATTN_LD,
                                          (long long)N_ * 3 * C_,
                                          (long long)N_ * C_,
                                          nullptr, nullptr, 1.0f);
    }

    // 7) permute (transpose(0,2,1).reshape)
    {
        long long total = (long long)ROWS * C_;
        permute_kernel<<<(unsigned)((total + 255) / 256), 256>>>(y, yp);
    }

    // 8) x1 = 2*(yp @ proj_w^T + proj_b)
    {
        dim3 grid((C_ + BN - 1) / BN, (ROWS + BM - 1) / BM, 1);
        sgemm_kernel<1, 1><<<grid, 256>>>(yp, proj_w, x1,
                                          ROWS, C_, C_,
                                          C_, C_, C_,
                                          0, 0, 0, proj_b, nullptr, 1.0f);
    }

    // 9) LN2
    layernorm_kernel<<<ROWS, 256>>>(x1, n2w, n2b, m0);

    // 10) m1 = gelu(m0 @ fc1_w^T + fc1_b)   [18464 x 3072], K=768
    {
        dim3 grid((H_ + BN - 1) / BN, (ROWS + BM - 1) / BM, 1);
        sgemm_kernel<1, 2><<<grid, 256>>>(m0, fc1_w, m1,
                                          ROWS, H_, C_,
                                          C_, C_, H_,
                                          0, 0, 0, fc1_b, nullptr, 1.0f);
    }

    // 11) out = x1 + m1 @ fc2_w^T + fc2_b   [18464 x 768], K=3072
    {
        dim3 grid((C_ + BN - 1) / BN, (ROWS + BM - 1) / BM, 1);
        sgemm_kernel<1, 3><<<grid, 256>>>(m1, fc2_w, out,
                                          ROWS, C_, H_,
                                          H_, H_, C_,
                                          0, 0, 0, fc2_b, x1, 1.0f);
    }
}